// round 10
// baseline (speedup 1.0000x reference)
#include <cuda_runtime.h>
#include <cstdint>

// ExodusNet: per-timestep dense (32 -> 1), ExpLeak scan, LIF scan with
// SingleSpike + MembraneSubtract.  x: (B, 32, 100) fp32 (t innermost),
// w: (32) fp32, out: (B, 100) fp32 of 0/1 spikes.
//
// R10: warp-autonomous 2-stage cp.async.bulk pipeline (as R9, 70.1us), with:
//   - 2 contiguous rows (25.6 KB) per bulk copy -> half the TMA/mbarrier ops
//   - spike write-out via one bulk S2G copy (3200 B contiguous) instead of STG
//   - ish stride 101 -> 100 (contiguous spike block; scan still conflict-free)
// FMA / scan orderings bitwise identical to all rel_err==0 kernels.

namespace {

constexpr int T_STEPS    = 100;
constexpr int F_DIM      = 32;
constexpr int ROW_FLOATS = F_DIM * T_STEPS;        // 3200 floats per row
constexpr int ROW_BYTES  = ROW_FLOATS * 4;         // 12800
constexpr int RPC        = 2;                      // rows per bulk copy
constexpr int COPY_BYTES = RPC * ROW_BYTES;        // 25600
constexpr int THREADS    = 64;                     // 2 warps
constexpr int NWARP      = THREADS / 32;
constexpr int B_PER_WARP = 8;
constexpr int N_COPIES   = B_PER_WARP / RPC;       // 4
constexpr int BPB        = NWARP * B_PER_WARP;     // 16
constexpr int NSTAGE     = 2;
constexpr int ISTRIDE    = 100;                    // contiguous spike rows

// dynamic smem layout (bytes)
constexpr int WSH_OFF   = 0;                                    // 32 floats
constexpr int MBAR_OFF  = 128;                                  // NWARP*NSTAGE*8
constexpr int ISH_OFF   = 192;
constexpr int ISH_BYTES = BPB * ISTRIDE * 4;                    // 6400
constexpr int RING_OFF  = ISH_OFF + ISH_BYTES;                  // 6592 (16B mult)
constexpr int SMEM_BYTES = RING_OFF + NWARP * NSTAGE * COPY_BYTES;  // 108992

__device__ __forceinline__ float alpha_f() { return (float)0.9048374180359595; }
__device__ __forceinline__ float one_m_a() { return (float)(1.0 - 0.9048374180359595); }

__device__ __forceinline__ uint32_t smem_u32(const void* p) {
    uint32_t a;
    asm("{ .reg .u64 t; cvta.to.shared.u64 t, %1; cvt.u32.u64 %0, t; }"
        : "=r"(a) : "l"(p));
    return a;
}
__device__ __forceinline__ void mbar_init(uint32_t mbar, uint32_t cnt) {
    asm volatile("mbarrier.init.shared.b64 [%0], %1;" :: "r"(mbar), "r"(cnt) : "memory");
}
__device__ __forceinline__ void mbar_expect_tx(uint32_t mbar, uint32_t bytes) {
    asm volatile("mbarrier.arrive.expect_tx.shared.b64 _, [%0], %1;"
                 :: "r"(mbar), "r"(bytes) : "memory");
}
__device__ __forceinline__ void bulk_copy_g2s(uint32_t dst_smem, const void* src_gmem,
                                              uint32_t bytes, uint32_t mbar) {
    asm volatile(
        "cp.async.bulk.shared::cluster.global.mbarrier::complete_tx::bytes "
        "[%0], [%1], %2, [%3];"
        :: "r"(dst_smem), "l"(src_gmem), "r"(bytes), "r"(mbar) : "memory");
}
__device__ __forceinline__ void bulk_copy_s2g(void* dst_gmem, uint32_t src_smem,
                                              uint32_t bytes) {
    asm volatile(
        "cp.async.bulk.global.shared::cta.bulk_group [%0], [%1], %2;"
        :: "l"(dst_gmem), "r"(src_smem), "r"(bytes) : "memory");
}
__device__ __forceinline__ void mbar_wait_parity(uint32_t mbar, uint32_t parity) {
    asm volatile(
        "{\n\t"
        ".reg .pred P1;\n\t"
        "WAIT_LOOP_%=:\n\t"
        "mbarrier.try_wait.parity.acquire.cta.shared::cta.b64 P1, [%0], %1, 0x989680;\n\t"
        "@P1 bra.uni WAIT_DONE_%=;\n\t"
        "bra.uni WAIT_LOOP_%=;\n\t"
        "WAIT_DONE_%=:\n\t"
        "}"
        :: "r"(mbar), "r"(parity) : "memory");
}

__global__ __launch_bounds__(THREADS)
void exodus_kernel(const float* __restrict__ x,
                   const float* __restrict__ w,
                   float* __restrict__ out,
                   int B)
{
    extern __shared__ __align__(16) unsigned char smem_raw[];
    float* wsh = reinterpret_cast<float*>(smem_raw + WSH_OFF);
    float* ish = reinterpret_cast<float*>(smem_raw + ISH_OFF);

    const uint32_t smem_base = smem_u32(smem_raw);
    const int tid  = threadIdx.x;
    const int warp = tid >> 5;
    const int lane = tid & 31;
    const int b0   = blockIdx.x * BPB;

    if (tid < F_DIM) wsh[tid] = w[tid];
    if (tid == 0) {
        #pragma unroll
        for (int m = 0; m < NWARP * NSTAGE; ++m)
            mbar_init(smem_base + MBAR_OFF + m * 8, 1);
    }
    __syncthreads();   // only block-wide barrier

    const int      wb_base   = b0 + warp * B_PER_WARP;
    const uint32_t ring_base = smem_base + RING_OFF + warp * (NSTAGE * COPY_BYTES);
    const uint32_t mbar_base = smem_base + MBAR_OFF + warp * (NSTAGE * 8);
    float* ish_w = ish + warp * (B_PER_WARP * ISTRIDE);
    const bool full_tile = (wb_base + B_PER_WARP) <= B;

    // ---------------- Phase 1: TMA-streamed weighted currents ------------------
    // prologue: fill both stages (2 rows per copy)
    if (lane == 0) {
        #pragma unroll
        for (int s = 0; s < NSTAGE; ++s) {
            const int b = wb_base + s * RPC;
            if (b < B) {
                const uint32_t bytes =
                    (b + RPC <= B) ? COPY_BYTES : (uint32_t)(B - b) * ROW_BYTES;
                mbar_expect_tx(mbar_base + s * 8, bytes);
                bulk_copy_g2s(ring_base + s * COPY_BYTES,
                              x + (size_t)b * ROW_FLOATS, bytes, mbar_base + s * 8);
            }
        }
    }

    #pragma unroll
    for (int i = 0; i < N_COPIES; ++i) {
        const int brow = wb_base + i * RPC;
        if (brow >= B) break;
        const int s  = i & 1;
        const int ph = (i >> 1) & 1;
        mbar_wait_parity(mbar_base + s * 8, (uint32_t)ph);

        if (lane < 25) {
            const float* stage = reinterpret_cast<const float*>(
                smem_raw + RING_OFF + warp * (NSTAGE * COPY_BYTES) + s * COPY_BYTES);
            #pragma unroll
            for (int r = 0; r < RPC; ++r) {
                if (brow + r >= B) break;
                const float* base = stage + r * ROW_FLOATS + 4 * lane;
                float4 acc = make_float4(0.f, 0.f, 0.f, 0.f);
                #pragma unroll
                for (int f = 0; f < F_DIM; ++f) {
                    const float4 xa = *reinterpret_cast<const float4*>(base + f * T_STEPS);
                    const float wf = wsh[f];
                    acc.x = fmaf(xa.x, wf, acc.x);
                    acc.y = fmaf(xa.y, wf, acc.y);
                    acc.z = fmaf(xa.z, wf, acc.z);
                    acc.w = fmaf(xa.w, wf, acc.w);
                }
                float* ip = ish_w + (i * RPC + r) * ISTRIDE + 4 * lane;
                ip[0] = acc.x;
                ip[1] = acc.y;
                ip[2] = acc.z;
                ip[3] = acc.w;
            }
        }
        __syncwarp();   // stage fully read before reissue

        const int nxt = i + NSTAGE;
        if (lane == 0 && nxt < N_COPIES) {
            const int nb = wb_base + nxt * RPC;
            if (nb < B) {
                const uint32_t bytes =
                    (nb + RPC <= B) ? COPY_BYTES : (uint32_t)(B - nb) * ROW_BYTES;
                mbar_expect_tx(mbar_base + s * 8, bytes);
                bulk_copy_g2s(ring_base + s * COPY_BYTES,
                              x + (size_t)nb * ROW_FLOATS, bytes, mbar_base + s * 8);
            }
        }
    }
    __syncwarp();

    // ---------------- Phase 2: sequential scans, warp-local (8 lanes) ----------
    // syn[t] = a*syn[t-1] + i[t]
    // v[t]   = a*v[t-1] + (1-a)*syn[t];  s = (v >= 1);  v -= s
    // lanes 0..7, rows stride 100 -> banks (4*lane + t) % 32, conflict-free.
    if (lane < B_PER_WARP && (wb_base + lane) < B) {
        float* ip = ish_w + lane * ISTRIDE;
        float syn = 0.f, v = 0.f;
        #pragma unroll 4
        for (int t = 0; t < T_STEPS; ++t) {
            const float i = ip[t];
            syn = fmaf(alpha_f(), syn, i);
            v   = fmaf(alpha_f(), v, one_m_a() * syn);
            const float s = (v >= 1.0f) ? 1.0f : 0.0f;
            v -= s;
            ip[t] = s;
        }
    }
    // make generic-proxy STS visible to the async proxy, then sync the warp
    asm volatile("fence.proxy.async.shared::cta;" ::: "memory");
    __syncwarp();

    // ---------------- Phase 3: spike write-out ---------------------------------
    if (full_tile) {
        // one contiguous 8*100*4 = 3200B bulk S2G copy per warp
        if (lane == 0) {
            bulk_copy_s2g(out + (size_t)wb_base * T_STEPS,
                          smem_base + ISH_OFF +
                              (uint32_t)(warp * B_PER_WARP * ISTRIDE * 4),
                          (uint32_t)(B_PER_WARP * ISTRIDE * 4));
            asm volatile("cp.async.bulk.commit_group;" ::: "memory");
            asm volatile("cp.async.bulk.wait_group 0;" ::: "memory");
        }
    } else {
        for (int k = 0; k < B_PER_WARP; ++k) {
            const int b = wb_base + k;
            if (b >= B) break;
            float* op       = out + (size_t)b * T_STEPS;
            const float* ip = ish_w + k * ISTRIDE;
            #pragma unroll
            for (int j = 0; j < 4; ++j) {
                const int t = lane + 32 * j;
                if (t < T_STEPS) op[t] = ip[t];
            }
        }
    }
}

} // namespace

extern "C" void kernel_launch(void* const* d_in, const int* in_sizes, int n_in,
                              void* d_out, int out_size)
{
    const float* x = (const float*)d_in[0];
    const float* w = (const float*)d_in[1];
    float* out     = (float*)d_out;

    const int B = in_sizes[0] / ROW_FLOATS;   // 32768

    cudaFuncSetAttribute(exodus_kernel,
                         cudaFuncAttributeMaxDynamicSharedMemorySize, SMEM_BYTES);

    const int grid = (B + BPB - 1) / BPB;     // 2048
    exodus_kernel<<<grid, THREADS, SMEM_BYTES>>>(x, w, out, B);
}